// round 1
// baseline (speedup 1.0000x reference)
#include <cuda_runtime.h>

#define N_ 4
#define C_ 64
#define H_ 192
#define W_ 192
#define DIL_ 2

// Intermediate buffer for the dynamic-aggregation output (no cudaMalloc allowed).
__device__ float g_mid[N_ * C_ * H_ * W_];

// ---------------------------------------------------------------------------
// Stage 1: per-pixel dynamic 3x3 (dilation 2) aggregation.
// out[n,c,h,w] = sum_k x_pad[n,c,h+2(ki-1),w+2(kj-1)] * y[n, c*9+k, h, w]
// One thread per output element; y reads perfectly coalesced, x via L1/L2 reuse.
// ---------------------------------------------------------------------------
__global__ void dyn_agg_kernel(const float* __restrict__ x,
                               const float* __restrict__ y) {
    int t = blockIdx.x * blockDim.x + threadIdx.x;
    const int total = N_ * C_ * H_ * W_;
    if (t >= total) return;

    int w = t % W_;
    int h = (t / W_) % H_;
    int c = (t / (W_ * H_)) % C_;
    int n = t / (W_ * H_ * C_);

    const float* xb = x + ((n * C_ + c) * H_) * W_;
    // y index: ((n*C + c)*9 + k)*H*W + h*W + w
    int yb = (((n * C_ + c) * 9) * H_ + h) * W_ + w;

    float sum = 0.f;
#pragma unroll
    for (int i = 0; i < 3; i++) {
        int hh = h + (i - 1) * DIL_;
        bool hv = ((unsigned)hh < (unsigned)H_);
#pragma unroll
        for (int j = 0; j < 3; j++) {
            int ww = w + (j - 1) * DIL_;
            float xv = (hv && (unsigned)ww < (unsigned)W_) ? xb[hh * W_ + ww] : 0.f;
            float yv = y[yb + (i * 3 + j) * (H_ * W_)];
            sum += xv * yv;
        }
    }
    g_mid[t] = sum;
}

// ---------------------------------------------------------------------------
// Stage 2: 3x3 conv (pad 1) 64->64 channels + bias + LeakyReLU(0.2).
// One block per (n, h) output row; 192 threads = one w each.
// Each thread accumulates all 64 output channels in registers.
// Per c_in: stage 3 halo rows + the 576 weights into smem, then 576 FMAs/thread
// with broadcast LDS.128 weight reads (144 LDS per 576 FMA -> FMA-pipe bound).
// ---------------------------------------------------------------------------
__global__ void __launch_bounds__(192)
fuse_conv_kernel(const float* __restrict__ wgt,
                 const float* __restrict__ bias,
                 float* __restrict__ out) {
    const int h = blockIdx.x % H_;
    const int n = blockIdx.x / H_;
    const int tid = threadIdx.x;
    const int w = tid;

    __shared__ float s_in[3][W_ + 4];             // halo row buffer, offset +1
    __shared__ __align__(16) float s_w[9 * 64];   // weights for current c_in: [k][c_out]

    float acc[64];
#pragma unroll
    for (int i = 0; i < 64; i++) acc[i] = 0.f;

    for (int ci = 0; ci < C_; ci++) {
        const float* inb = g_mid + ((n * C_ + ci) * H_) * W_;

        // Cooperative load of 3 input rows (w from -1..192 => 194 entries each).
        for (int i = tid; i < 3 * 194; i += 192) {
            int r  = i / 194;
            int wi = (i % 194) - 1;
            int row = h + r - 1;
            float v = 0.f;
            if ((unsigned)row < (unsigned)H_ && (unsigned)wi < (unsigned)W_)
                v = inb[row * W_ + wi];
            s_in[r][wi + 1] = v;
        }
        // Weights for this c_in: s_w[k*64 + co] = wgt[(co*64 + ci)*9 + k]
        for (int i = tid; i < 576; i += 192) {
            int k  = i >> 6;
            int co = i & 63;
            s_w[i] = wgt[(co * C_ + ci) * 9 + k];
        }
        __syncthreads();

        float tap[9];
#pragma unroll
        for (int kk = 0; kk < 9; kk++) {
            int r = kk / 3;
            int j = kk % 3;
            tap[kk] = s_in[r][w + j];   // (w-1 + j) + 1 offset
        }

#pragma unroll
        for (int kk = 0; kk < 9; kk++) {
            float t = tap[kk];
            const float4* wv = (const float4*)&s_w[kk * 64];
#pragma unroll
            for (int q = 0; q < 16; q++) {
                float4 v = wv[q];       // broadcast LDS.128, conflict-free
                acc[q * 4 + 0] += t * v.x;
                acc[q * 4 + 1] += t * v.y;
                acc[q * 4 + 2] += t * v.z;
                acc[q * 4 + 3] += t * v.w;
            }
        }
        __syncthreads();
    }

#pragma unroll
    for (int co = 0; co < 64; co++) {
        float v = acc[co] + bias[co];
        v = (v >= 0.f) ? v : 0.2f * v;
        out[((n * C_ + co) * H_ + h) * W_ + w] = v;
    }
}

extern "C" void kernel_launch(void* const* d_in, const int* in_sizes, int n_in,
                              void* d_out, int out_size) {
    const float* x  = (const float*)d_in[0];   // [4,64,192,192]
    const float* y  = (const float*)d_in[1];   // [4,576,192,192]
    const float* fw = (const float*)d_in[2];   // [64,64,3,3]
    const float* fb = (const float*)d_in[3];   // [64]
    float* out = (float*)d_out;                // [4,64,192,192]

    const int total = N_ * C_ * H_ * W_;
    dyn_agg_kernel<<<(total + 255) / 256, 256>>>(x, y);
    fuse_conv_kernel<<<N_ * H_, 192>>>(fw, fb, out);
}

// round 5
// speedup vs baseline: 2.7924x; 2.7924x over previous
#include <cuda_runtime.h>
#include <cuda_bf16.h>
#include <cstdint>

#define N_ 4
#define C_ 64
#define H_ 192
#define W_ 192
#define DIL_ 2
#define HW_ (H_ * W_)            // 36864

// ---------------------------------------------------------------------------
// Device-global scratch (no cudaMalloc allowed).
// ---------------------------------------------------------------------------
__device__ float g_mid[N_ * C_ * H_ * W_];                       // stage-1 output
__device__ __align__(16) unsigned char g_wt_hi[9 * 8192];        // bf16 hi, swizzled [co][ci] tiles
__device__ __align__(16) unsigned char g_wt_lo[9 * 8192];        // bf16 lo, swizzled [co][ci] tiles

#define SW128(o) ((uint32_t)(o) ^ ((((uint32_t)(o)) >> 3) & 0x70u))

__device__ __forceinline__ uint32_t smem_u32(const void* p) {
    uint32_t a;
    asm("{ .reg .u64 t; cvta.to.shared.u64 t, %1; cvt.u32.u64 %0, t; }" : "=r"(a) : "l"(p));
    return a;
}
__device__ __forceinline__ void ldsm_x4(uint32_t* r, uint32_t addr) {
    asm volatile("ldmatrix.sync.aligned.m8n8.x4.shared.b16 {%0,%1,%2,%3}, [%4];"
                 : "=r"(r[0]), "=r"(r[1]), "=r"(r[2]), "=r"(r[3]) : "r"(addr));
}
// NON-trans: smem chunk is already n(rows) x k(cols) == B-fragment layout.
__device__ __forceinline__ void ldsm_x2(uint32_t* r, uint32_t addr) {
    asm volatile("ldmatrix.sync.aligned.m8n8.x2.shared.b16 {%0,%1}, [%2];"
                 : "=r"(r[0]), "=r"(r[1]) : "r"(addr));
}
__device__ __forceinline__ void mma_bf16(float* c, const uint32_t* a, const uint32_t* b) {
    asm volatile(
        "mma.sync.aligned.m16n8k16.row.col.f32.bf16.bf16.f32 "
        "{%0,%1,%2,%3}, {%4,%5,%6,%7}, {%8,%9}, {%0,%1,%2,%3};"
        : "+f"(c[0]), "+f"(c[1]), "+f"(c[2]), "+f"(c[3])
        : "r"(a[0]), "r"(a[1]), "r"(a[2]), "r"(a[3]), "r"(b[0]), "r"(b[1]));
}

// ---------------------------------------------------------------------------
// Stage 1: per-pixel dynamic 3x3 (dilation 2) aggregation. HBM-bound.
// ---------------------------------------------------------------------------
__global__ void dyn_agg_kernel(const float* __restrict__ x,
                               const float* __restrict__ y) {
    int t = blockIdx.x * blockDim.x + threadIdx.x;
    const int total = N_ * C_ * H_ * W_;
    if (t >= total) return;

    int w = t % W_;
    int h = (t / W_) % H_;
    int c = (t / HW_) % C_;
    int n = t / (HW_ * C_);

    const float* xb = x + (size_t)(n * C_ + c) * HW_;
    size_t yb = ((size_t)(n * C_ + c) * 9) * HW_ + h * W_ + w;

    float sum = 0.f;
#pragma unroll
    for (int i = 0; i < 3; i++) {
        int hh = h + (i - 1) * DIL_;
        bool hv = ((unsigned)hh < (unsigned)H_);
#pragma unroll
        for (int j = 0; j < 3; j++) {
            int ww = w + (j - 1) * DIL_;
            float xv = (hv && (unsigned)ww < (unsigned)W_) ? __ldg(xb + hh * W_ + ww) : 0.f;
            float yv = __ldg(y + yb + (size_t)(i * 3 + j) * HW_);
            sum += xv * yv;
        }
    }
    g_mid[t] = sum;
}

// ---------------------------------------------------------------------------
// Stage 1.5: split weights into bf16 hi/lo in the swizzled tile image:
// tile kk = [co:64 rows x ci:64 cols] bf16, 128B rows, SW128 swizzle.
// ---------------------------------------------------------------------------
__global__ void prep_w_kernel(const float* __restrict__ wgt) {
    int i = blockIdx.x * blockDim.x + threadIdx.x;   // 9*64*64 = 36864
    if (i >= 9 * 64 * 64) return;
    int kk = i >> 12;
    int co = (i >> 6) & 63;
    int ci = i & 63;
    float v = wgt[(co * C_ + ci) * 9 + kk];
    __nv_bfloat16 hi = __float2bfloat16(v);
    __nv_bfloat16 lo = __float2bfloat16(v - __bfloat162float(hi));
    uint32_t off = SW128((uint32_t)(co * 128 + ci * 2));
    *(__nv_bfloat16*)(g_wt_hi + kk * 8192 + off) = hi;
    *(__nv_bfloat16*)(g_wt_lo + kk * 8192 + off) = lo;
}

// ---------------------------------------------------------------------------
// Stage 2: warp-MMA implicit-GEMM conv (mma.sync m16n8k16 bf16, fp32 split).
// C[co=64, pix=128] per CTA; A = weights (co x ci), B = im2col pixels stored
// n(rows) x k(cols) and consumed via NON-trans ldmatrix (matches B fragment).
// K = 576 marched in 9 tap-chunks of 64.
// D += Ahi*Bhi + Ahi*Blo + Alo*Bhi  (lo*lo dropped, ~2^-18).
// smem: px_hi 16K | px_lo 16K | wt_hi 8K | wt_lo 8K = 48KB exactly.
// ---------------------------------------------------------------------------
#define S_PXHI 0
#define S_PXLO 16384
#define S_WTHI 32768
#define S_WTLO 40960
#define SMEM_SZ 49152

__global__ void __launch_bounds__(256)
conv_mma_kernel(const float* __restrict__ bias, float* __restrict__ out) {
    extern __shared__ unsigned char smem[];
    const uint32_t sb = smem_u32(smem);
    const int tid = threadIdx.x;
    const int wid = tid >> 5;
    const int lane = tid & 31;

    const int b  = blockIdx.x;           // 1152 = 4 * 96 * 3
    const int wt = b % 3;
    const int hp = (b / 3) % 96;
    const int n  = b / 288;
    const int h0 = hp * 2;
    const int w0 = wt * 64;

    // Warp tile: m-tile (16 c_out) = wid&3, n-half (64 pixels) = wid>>2.
    const int mt = wid & 3;
    const int nh = wid >> 2;

    float acc[32];
#pragma unroll
    for (int i = 0; i < 32; i++) acc[i] = 0.f;

    // Fill-thread invariants: pixel p = tid&127, ci parity = tid>>7.
    const int p   = tid & 127;
    const int cio = tid >> 7;
    const int pr  = p >> 6;
    const int pc  = p & 63;
    const uint32_t xr    = (uint32_t)((p & 7) << 4);
    const uint32_t pbase = (uint32_t)(p * 128);

    // ldmatrix address invariants (A = weights, x4 non-trans).
    const int g      = lane >> 3;
    const int arow   = mt * 16 + ((g & 1) << 3) + (lane & 7);
    const int abyte0 = ((g >> 1) << 4);
    const uint32_t axr = (uint32_t)((arow & 7) << 4);
    // B = pixels, x2 non-trans: threads 0-7 -> k-bytes 0..15, threads 8-15 -> +16.
    const int brow0  = nh * 64 + (lane & 7);
    const int bbyte0 = ((lane >> 3) & 1) << 4;

    for (int kk = 0; kk < 9; kk++) {
        const int dh = kk / 3 - 1;
        const int dw = kk % 3 - 1;

        // ---- fill pixel tile (128 x 64 ci), bf16 hi/lo, swizzled ----
        {
            const int ph = h0 + pr + dh;
            const int pw = w0 + pc + dw;
            const bool ok = ((unsigned)ph < (unsigned)H_) && ((unsigned)pw < (unsigned)W_);
            const float* src = g_mid + ((size_t)(n * C_ + cio) * H_ + ph) * W_ + pw;
#pragma unroll
            for (int it = 0; it < 32; it++) {
                const int ci = cio + it * 2;
                float v = ok ? src[(size_t)it * 2 * HW_] : 0.f;
                __nv_bfloat16 hi = __float2bfloat16(v);
                __nv_bfloat16 lo = __float2bfloat16(v - __bfloat162float(hi));
                uint32_t off = (pbase + (uint32_t)(ci * 2)) ^ xr;
                *(__nv_bfloat16*)(smem + S_PXHI + off) = hi;
                *(__nv_bfloat16*)(smem + S_PXLO + off) = lo;
            }
        }
        // ---- copy weight tiles (pre-swizzled, 8KB each) ----
        {
            const uint4* gh = (const uint4*)(g_wt_hi + kk * 8192);
            const uint4* gl = (const uint4*)(g_wt_lo + kk * 8192);
            uint4* sh = (uint4*)(smem + S_WTHI);
            uint4* sl = (uint4*)(smem + S_WTLO);
#pragma unroll
            for (int i = 0; i < 2; i++) {
                sh[tid + i * 256] = gh[tid + i * 256];
                sl[tid + i * 256] = gl[tid + i * 256];
            }
        }
        __syncthreads();

        // ---- MMA over this chunk: 4 k-steps of 16 ----
#pragma unroll
        for (int ks = 0; ks < 4; ks++) {
            uint32_t aoff = (uint32_t)(arow * 128 + ks * 32 + abyte0) ^ axr;
            uint32_t ah[4], al[4];
            ldsm_x4(ah, sb + S_WTHI + aoff);
            ldsm_x4(al, sb + S_WTLO + aoff);
#pragma unroll
            for (int nt = 0; nt < 8; nt++) {
                const int brow = brow0 + nt * 8;
                uint32_t boff = (uint32_t)(brow * 128 + ks * 32 + bbyte0)
                                ^ (uint32_t)((brow & 7) << 4);
                uint32_t bh[2], bl[2];
                ldsm_x2(bh, sb + S_PXHI + boff);
                ldsm_x2(bl, sb + S_PXLO + boff);
                mma_bf16(acc + nt * 4, ah, bh);
                mma_bf16(acc + nt * 4, ah, bl);
                mma_bf16(acc + nt * 4, al, bh);
            }
        }
        __syncthreads();
    }

    // ---- epilogue: bias + LeakyReLU, float2 stores along w ----
    const int co0 = mt * 16 + (lane >> 2);          // rows co0 and co0+8
    const float b0 = __ldg(bias + co0);
    const float b1 = __ldg(bias + co0 + 8);
#pragma unroll
    for (int nt = 0; nt < 8; nt++) {
        const int pix = nh * 64 + nt * 8 + ((lane & 3) << 1);
        const int hh = h0 + (pix >> 6);
        const int ww = w0 + (pix & 63);
        {
            float v0 = acc[nt * 4 + 0] + b0;
            float v1 = acc[nt * 4 + 1] + b0;
            v0 = (v0 >= 0.f) ? v0 : 0.2f * v0;
            v1 = (v1 >= 0.f) ? v1 : 0.2f * v1;
            *(float2*)(out + (((size_t)n * C_ + co0) * H_ + hh) * W_ + ww) =
                make_float2(v0, v1);
        }
        {
            float v0 = acc[nt * 4 + 2] + b1;
            float v1 = acc[nt * 4 + 3] + b1;
            v0 = (v0 >= 0.f) ? v0 : 0.2f * v0;
            v1 = (v1 >= 0.f) ? v1 : 0.2f * v1;
            *(float2*)(out + (((size_t)n * C_ + co0 + 8) * H_ + hh) * W_ + ww) =
                make_float2(v0, v1);
        }
    }
}

// ---------------------------------------------------------------------------
extern "C" void kernel_launch(void* const* d_in, const int* in_sizes, int n_in,
                              void* d_out, int out_size) {
    const float* x  = (const float*)d_in[0];   // [4,64,192,192]
    const float* y  = (const float*)d_in[1];   // [4,576,192,192]
    const float* fw = (const float*)d_in[2];   // [64,64,3,3]
    const float* fb = (const float*)d_in[3];   // [64]
    float* out = (float*)d_out;                // [4,64,192,192]

    const int total = N_ * C_ * H_ * W_;
    dyn_agg_kernel<<<(total + 255) / 256, 256>>>(x, y);
    prep_w_kernel<<<(9 * 64 * 64 + 255) / 256, 256>>>(fw);
    conv_mma_kernel<<<N_ * 96 * 3, 256, SMEM_SZ>>>(fb, out);
}